// round 1
// baseline (speedup 1.0000x reference)
#include <cuda_runtime.h>

#define NQ      12
#define DIM     4096
#define DEPTH   8
#define NCLASS  10
#define NT      256
#define PER     16   // DIM / NT

// XOR swizzle: bank = (i ^ (i>>4)) & 31 is bijective on lanes for all three
// stage access patterns -> conflict-free scalar LDS/STS everywhere.
__device__ __forceinline__ int swz(int i) { return i ^ ((i >> 4) & 31); }

__global__ __launch_bounds__(NT) void vqc_kernel(const float* __restrict__ X,
                                                 const float* __restrict__ W,
                                                 float* __restrict__ out) {
    __shared__ float sv[DIM];
    __shared__ float wc[DEPTH * NQ], ws[DEPTH * NQ];
    __shared__ float e0[NQ], e1[NQ];
    __shared__ float red[NT / 32][NCLASS];

    const int t = threadIdx.x;
    const int b = blockIdx.x;

    // Precompute cos/sin of half-angles for all variational weights (shared
    // across batch) and the per-sample encoding qubit factors.
    if (t < DEPTH * NQ) {
        float s_, c_;
        sincosf(0.5f * W[t], &s_, &c_);
        wc[t] = c_;
        ws[t] = s_;
    }
    if (t >= 128 && t < 128 + NQ) {
        const int q = t - 128;
        float s_, c_;
        sincosf(0.5f * X[b * NQ + q], &s_, &c_);
        const float r = 0.7071067811865476f;  // 1/sqrt(2)
        e0[q] = (c_ - s_) * r;   // amplitude factor for bit = 0
        e1[q] = (c_ + s_) * r;   // amplitude factor for bit = 1
    }
    __syncthreads();

    // ---- init: product state after H + data-encoding RY layer ----
    // index i = (j<<8) | t ; qubit q <-> bit (11-q)
    float base = 1.0f;
#pragma unroll
    for (int q = 4; q < NQ; q++)
        base *= ((t >> (11 - q)) & 1) ? e1[q] : e0[q];
#pragma unroll
    for (int j = 0; j < PER; j++) {
        float a = base;
#pragma unroll
        for (int q = 0; q < 4; q++)
            a *= ((j >> (3 - q)) & 1) ? e1[q] : e0[q];
        sv[swz((j << 8) | t)] = a;
    }
    __syncthreads();

    float r[PER];

    for (int k = 0; k < DEPTH; k++) {
        const float* kc = wc + k * NQ;
        const float* ks = ws + k * NQ;

        // ---- stage 1: fused CNOT permutation gather + RY on qubits 0..3 ----
        // All even CNOTs:  e(i) = i ^ ((i>>1) & 0x555)
        // All odd  CNOTs:  o(i) = i ^ ((i>>1) & 0x2AA)
        // layer gather index = e(o(i))
#pragma unroll
        for (int j = 0; j < PER; j++) {
            int i  = (j << 8) | t;
            int oo = i ^ ((i >> 1) & 0x2AA);
            int ee = oo ^ ((oo >> 1) & 0x555);
            r[j] = sv[swz(ee)];
        }
        __syncthreads();
#pragma unroll
        for (int q = 0; q < 4; q++) {
            const float c = kc[q], s = ks[q];
            const int m = 8 >> q;              // qubit q <-> j bit (3-q)
#pragma unroll
            for (int j = 0; j < PER; j++) {
                if (!(j & m)) {
                    float a0 = r[j], a1 = r[j | m];
                    r[j]     = c * a0 - s * a1;
                    r[j | m] = s * a0 + c * a1;
                }
            }
        }
        {
            const int A = swz(t);
#pragma unroll
            for (int j = 0; j < PER; j++)
                sv[A ^ (j << 8) ^ ((j & 1) << 4)] = r[j];   // swz((j<<8)|t)
        }
        __syncthreads();

        // ---- stage 2: RY on qubits 4..7 (index bits 7..4) ----
        {
            const int A = swz(((t >> 4) << 8) | (t & 15));
#pragma unroll
            for (int j = 0; j < PER; j++)
                r[j] = sv[A ^ (j << 4) ^ j];               // swz(base|(j<<4))
#pragma unroll
            for (int q = 0; q < 4; q++) {
                const float c = kc[4 + q], s = ks[4 + q];
                const int m = 8 >> q;
#pragma unroll
                for (int j = 0; j < PER; j++) {
                    if (!(j & m)) {
                        float a0 = r[j], a1 = r[j | m];
                        r[j]     = c * a0 - s * a1;
                        r[j | m] = s * a0 + c * a1;
                    }
                }
            }
#pragma unroll
            for (int j = 0; j < PER; j++)
                sv[A ^ (j << 4) ^ j] = r[j];
        }
        __syncthreads();

        // ---- stage 3: RY on qubits 8..11 (index bits 3..0) ----
        {
            const int A = swz(t << 4);
#pragma unroll
            for (int j = 0; j < PER; j++)
                r[j] = sv[A ^ j];                          // swz((t<<4)|j)
#pragma unroll
            for (int q = 0; q < 4; q++) {
                const float c = kc[8 + q], s = ks[8 + q];
                const int m = 8 >> q;
#pragma unroll
                for (int j = 0; j < PER; j++) {
                    if (!(j & m)) {
                        float a0 = r[j], a1 = r[j | m];
                        r[j]     = c * a0 - s * a1;
                        r[j | m] = s * a0 + c * a1;
                    }
                }
            }
#pragma unroll
            for (int j = 0; j < PER; j++)
                sv[A ^ j] = r[j];
        }
        __syncthreads();
    }

    // ---- measurement: <Z_p> = sum_i amp(i)^2 * (1 - 2*bit_{11-p}(i)) ----
    float loc[NCLASS];
#pragma unroll
    for (int p = 0; p < NCLASS; p++) loc[p] = 0.0f;
#pragma unroll
    for (int j = 0; j < PER; j++) {
        const int i = (j << 8) | t;
        const float v = sv[swz(i)];
        const float p2 = v * v;
#pragma unroll
        for (int p = 0; p < NCLASS; p++)
            loc[p] += ((i >> (11 - p)) & 1) ? -p2 : p2;
    }
#pragma unroll
    for (int p = 0; p < NCLASS; p++) {
        float v = loc[p];
#pragma unroll
        for (int o = 16; o > 0; o >>= 1)
            v += __shfl_xor_sync(0xffffffffu, v, o);
        loc[p] = v;
    }
    if ((t & 31) == 0) {
#pragma unroll
        for (int p = 0; p < NCLASS; p++) red[t >> 5][p] = loc[p];
    }
    __syncthreads();
    if (t < NCLASS) {
        float acc = 0.0f;
#pragma unroll
        for (int w = 0; w < NT / 32; w++) acc += red[w][t];
        out[b * NCLASS + t] = acc;
    }
}

extern "C" void kernel_launch(void* const* d_in, const int* in_sizes, int n_in,
                              void* d_out, int out_size) {
    const float* X = (const float*)d_in[0];        // [4096, 12] fp32
    const float* W = (const float*)d_in[1];        // [8, 12]    fp32
    float* out = (float*)d_out;                    // [4096, 10] fp32
    const int batch = in_sizes[0] / NQ;
    vqc_kernel<<<batch, NT>>>(X, W, out);
}

// round 2
// speedup vs baseline: 1.2478x; 1.2478x over previous
#include <cuda_runtime.h>

#define NQ      12
#define DIM     4096
#define DEPTH   8
#define NCLASS  10
#define NT      256
#define PER     16   // DIM / NT

typedef unsigned long long u64;

// XOR swizzle: conflict-free scalar LDS/STS for all stage access patterns.
__device__ __host__ constexpr int swz_c(int i) { return i ^ ((i >> 4) & 31); }

// Full CNOT-layer + swizzle map (GF(2)-linear):  F = swz ∘ e ∘ o
__device__ __host__ constexpr int Fmap(int i) {
    int o = i ^ ((i >> 1) & 0x2AA);   // odd-pair CNOTs
    int e = o ^ ((o >> 1) & 0x555);   // even-pair CNOTs
    return swz_c(e);
}

#define PACK2(d, x, y)   asm("mov.b64 %0, {%1,%2};" : "=l"(d) : "f"(x), "f"(y))
#define UNPACK2(x, y, d) asm("mov.b64 {%0,%1}, %2;" : "=f"(x), "=f"(y) : "l"(d))
#define MUL2(d, a, b)    asm("mul.rn.f32x2 %0, %1, %2;" : "=l"(d) : "l"(a), "l"(b))
#define FMA2(d, a, b, c) asm("fma.rn.f32x2 %0, %1, %2, %3;" : "=l"(d) : "l"(a), "l"(b), "l"(c))

// Apply 4 commuting RY butterflies (qubit masks 8,4,2,1 on index j) to v[16].
// Intra-pair qubit (mask 1) done scalar; masks 8/4/2 done with packed f32x2.
__device__ __forceinline__ void butterfly16(const float* __restrict__ kc,
                                            const float* __restrict__ ks,
                                            int q0, float* v) {
    // qubit q0+3  <->  j mask 1 (intra-pair): scalar
    {
        const float c = kc[q0 + 3], s = ks[q0 + 3];
#pragma unroll
        for (int k = 0; k < 8; k++) {
            float x = v[2 * k], y = v[2 * k + 1];
            v[2 * k]     = fmaf(c, x, -s * y);
            v[2 * k + 1] = fmaf(c, y,  s * x);
        }
    }
    // pack along j bit0
    u64 P[8];
#pragma unroll
    for (int k = 0; k < 8; k++) PACK2(P[k], v[2 * k], v[2 * k + 1]);

    // qubits q0+0..q0+2  <->  k masks 4,2,1: packed
#pragma unroll
    for (int q = 0; q < 3; q++) {
        const float c = kc[q0 + q], s = ks[q0 + q], ns = -s;
        u64 C2, S2, N2;
        PACK2(C2, c, c);
        PACK2(S2, s, s);
        PACK2(N2, ns, ns);
        const int m = 4 >> q;
#pragma unroll
        for (int k = 0; k < 8; k++) {
            if (!(k & m)) {
                u64 t1, t2;
                MUL2(t1, N2, P[k | m]);
                MUL2(t2, S2, P[k]);
                FMA2(P[k],     C2, P[k],     t1);
                FMA2(P[k | m], C2, P[k | m], t2);
            }
        }
    }
#pragma unroll
    for (int k = 0; k < 8; k++) UNPACK2(v[2 * k], v[2 * k + 1], P[k]);
}

__global__ __launch_bounds__(NT, 3) void vqc_kernel(const float* __restrict__ X,
                                                    const float* __restrict__ W,
                                                    float* __restrict__ out) {
    __shared__ float sv[2][DIM];
    __shared__ float wc[DEPTH * NQ], ws[DEPTH * NQ];
    __shared__ float e0[NQ], e1[NQ];
    __shared__ float red[NT / 32][NCLASS];

    const int t = threadIdx.x;
    const int b = blockIdx.x;

    if (t < DEPTH * NQ) {
        float s_, c_;
        sincosf(0.5f * W[t], &s_, &c_);
        wc[t] = c_;
        ws[t] = s_;
    }
    if (t >= 128 && t < 128 + NQ) {
        const int q = t - 128;
        float s_, c_;
        sincosf(0.5f * X[b * NQ + q], &s_, &c_);
        const float r = 0.7071067811865476f;  // 1/sqrt(2)
        e0[q] = (c_ - s_) * r;
        e1[q] = (c_ + s_) * r;
    }
    __syncthreads();

    // ---- init: product state after H + encoding RY (i = (j<<8)|t) ----
    float base = 1.0f;
#pragma unroll
    for (int q = 4; q < NQ; q++)
        base *= ((t >> (11 - q)) & 1) ? e1[q] : e0[q];
#pragma unroll
    for (int j = 0; j < PER; j++) {
        float a = base;
#pragma unroll
        for (int q = 0; q < 4; q++)
            a *= ((j >> (3 - q)) & 1) ? e1[q] : e0[q];
        sv[0][swz_c((j << 8) | t)] = a;
    }
    __syncthreads();

    const int Ft = Fmap(t);               // runtime part of gather address
    const int A1 = swz_c(t);              // stage-1 store base
    const int A2 = swz_c(((t >> 4) << 8) | (t & 15));
    const int A3 = swz_c(t << 4);

    float v[PER];

#pragma unroll 1
    for (int k = 0; k < DEPTH; k++) {
        const float* kc = wc + k * NQ;
        const float* ks = ws + k * NQ;
        const int a = k & 1, bb = a ^ 1;

        // ---- stage 1: CNOT-layer gather (linear map) + RY qubits 0..3 ----
#pragma unroll
        for (int j = 0; j < PER; j++)
            v[j] = sv[a][Ft ^ Fmap(j << 8)];
        butterfly16(kc, ks, 0, v);
#pragma unroll
        for (int j = 0; j < PER; j++)
            sv[bb][A1 ^ (j << 8) ^ ((j & 1) << 4)] = v[j];
        __syncthreads();

        // ---- stage 2: RY qubits 4..7 (index bits 7..4) ----
#pragma unroll
        for (int j = 0; j < PER; j++)
            v[j] = sv[bb][A2 ^ (j << 4) ^ j];
        butterfly16(kc, ks, 4, v);
#pragma unroll
        for (int j = 0; j < PER; j++)
            sv[bb][A2 ^ (j << 4) ^ j] = v[j];
        __syncthreads();

        // ---- stage 3: RY qubits 8..11 (index bits 3..0) ----
#pragma unroll
        for (int j = 0; j < PER; j++)
            v[j] = sv[bb][A3 ^ j];
        butterfly16(kc, ks, 8, v);
#pragma unroll
        for (int j = 0; j < PER; j++)
            sv[bb][A3 ^ j] = v[j];
        __syncthreads();
    }

    // final state lives in sv[(DEPTH)&1 ^ ... ] = sv[0] for DEPTH=8
    const float* fin = sv[DEPTH & 1 ? 1 : 0];  // layer k writes to (k&1)^1; k=7 -> 0

    // ---- measurement: <Z_p> = sum_i amp^2 * (1 - 2*bit_{11-p}(i)) ----
    float sgn[6];
#pragma unroll
    for (int p = 4; p < NCLASS; p++)
        sgn[p - 4] = ((t >> (11 - p)) & 1) ? -1.0f : 1.0f;

    float loc[NCLASS];
#pragma unroll
    for (int p = 0; p < NCLASS; p++) loc[p] = 0.0f;
#pragma unroll
    for (int j = 0; j < PER; j++) {
        const float w0 = fin[swz_c((j << 8) | t)];
        const float p2 = w0 * w0;
#pragma unroll
        for (int p = 0; p < 4; p++)
            loc[p] += ((j >> (3 - p)) & 1) ? -p2 : p2;   // compile-time sign
#pragma unroll
        for (int p = 4; p < NCLASS; p++)
            loc[p] = fmaf(sgn[p - 4], p2, loc[p]);
    }
#pragma unroll
    for (int p = 0; p < NCLASS; p++) {
        float x = loc[p];
#pragma unroll
        for (int o = 16; o > 0; o >>= 1)
            x += __shfl_xor_sync(0xffffffffu, x, o);
        loc[p] = x;
    }
    if ((t & 31) == 0) {
#pragma unroll
        for (int p = 0; p < NCLASS; p++) red[t >> 5][p] = loc[p];
    }
    __syncthreads();
    if (t < NCLASS) {
        float acc = 0.0f;
#pragma unroll
        for (int w = 0; w < NT / 32; w++) acc += red[w][t];
        out[b * NCLASS + t] = acc;
    }
}

extern "C" void kernel_launch(void* const* d_in, const int* in_sizes, int n_in,
                              void* d_out, int out_size) {
    const float* X = (const float*)d_in[0];   // [4096, 12] fp32
    const float* W = (const float*)d_in[1];   // [8, 12]    fp32
    float* out = (float*)d_out;               // [4096, 10] fp32
    const int batch = in_sizes[0] / NQ;
    vqc_kernel<<<batch, NT>>>(X, W, out);
}

// round 3
// speedup vs baseline: 1.3815x; 1.1072x over previous
#include <cuda_runtime.h>

#define DEPTH   8
#define NCLASS  10
#define NT      128
#define NE      2048   // statevector as 2048 float2 elements (index bit 0 inside)

typedef unsigned long long u64;

// Element-space XOR swizzle: conflict-free 64-bit LDS/STS for all tilings.
__device__ __host__ constexpr int es(int e)   { return e ^ ((e >> 4) & 15); }
// CNOT-layer gather in element space: old_element = Emap(new_element).
// Derived from G = e-CNOTs ∘ o-CNOTs; component swap handled separately.
__device__ __host__ constexpr int Emap(int e) { return e ^ (e >> 1) ^ ((e >> 2) & 0x2AA); }

#define PACK2(d,x,y)   asm("mov.b64 %0,{%1,%2};" : "=l"(d) : "f"(x),"f"(y))
#define UNPACK2(x,y,d) asm("mov.b64 {%0,%1},%2;" : "=f"(x),"=f"(y) : "l"(d))
#define MUL2(d,a,b)    asm("mul.rn.f32x2 %0,%1,%2;" : "=l"(d) : "l"(a),"l"(b))
#define FMA2(d,a,b,c)  asm("fma.rn.f32x2 %0,%1,%2,%3;" : "=l"(d) : "l"(a),"l"(b),"l"(c))

// Packed RY butterfly on 16 float2 registers along register-bit mask m.
__device__ __forceinline__ void bfly16(u64* P, int m, u64 C2, u64 S2, u64 N2) {
#pragma unroll
    for (int k = 0; k < 16; k++)
        if (!(k & m)) {
            u64 t1, t2;
            MUL2(t1, N2, P[k | m]);   // -s * a1
            MUL2(t2, S2, P[k]);       //  s * a0
            FMA2(P[k],     C2, P[k],     t1);   // c*a0 - s*a1
            FMA2(P[k | m], C2, P[k | m], t2);   // c*a1 + s*a0
        }
}

__global__ __launch_bounds__(NT, 6) void vqc_kernel(const float* __restrict__ X,
                                                    const float* __restrict__ W,
                                                    float* __restrict__ out) {
    __shared__ u64 buf[2][NE];
    __shared__ u64 cc2[DEPTH * 12], ss2[DEPTH * 12], ns2[DEPTH * 12];
    __shared__ float enc0[12], enc1[12];
    __shared__ float red[NT / 32][NCLASS];

    const int t = threadIdx.x;

    // ---- setup: packed weight coefficients + per-sample encoding factors ----
    if (t < DEPTH * 12) {
        float s_, c_;
        sincosf(0.5f * W[t], &s_, &c_);
        float n_ = -s_;
        u64 a, b, c3;
        PACK2(a, c_, c_);  PACK2(b, s_, s_);  PACK2(c3, n_, n_);
        cc2[t] = a; ss2[t] = b; ns2[t] = c3;
    } else if (t < DEPTH * 12 + 12) {
        const int q = t - DEPTH * 12;
        float s_, c_;
        sincosf(0.5f * X[blockIdx.x * 12 + q], &s_, &c_);
        const float r = 0.7071067811865476f;
        enc0[q] = (c_ - s_) * r;
        enc1[q] = (c_ + s_) * r;
    }
    __syncthreads();

    // ---- init: product state (H + encoding RY), tiling A: e = (r<<7)|t ----
    float base = 1.0f;
#pragma unroll
    for (int q = 4; q <= 10; q++)
        base *= ((t >> (10 - q)) & 1) ? enc1[q] : enc0[q];
    const float bx = base * enc0[11], by = base * enc1[11];
#pragma unroll
    for (int r = 0; r < 16; r++) {
        float rf = 1.0f;
#pragma unroll
        for (int q = 0; q < 4; q++)
            rf *= ((r >> (3 - q)) & 1) ? enc1[q] : enc0[q];
        u64 v;
        float x = rf * bx, y = rf * by;
        PACK2(v, x, y);
        buf[0][es(r << 7) ^ es(t)] = v;
    }
    __syncthreads();

    // per-thread address bases (all maps GF(2)-linear -> base ^ compile-time const)
    const int gbase = es(Emap(t));                       // gather (tiling A)
    const bool sw   = ((t ^ (t >> 1)) & 1) != 0;         // gather pair swap = t0^t1
    const int aA    = es(t);                             // tiling A: e=(r<<7)|t
    const int aB    = es(((t >> 3) << 7) | (t & 7));     // tiling B: e=(th<<7)|(r<<3)|tl
    const int aC    = es(t << 4);                        // tiling C: e=(t<<4)|r

    u64 P[16];

#pragma unroll 1
    for (int k = 0; k < DEPTH; k++) {
        const u64* cc = cc2 + k * 12;
        const u64* ss = ss2 + k * 12;
        const u64* ns = ns2 + k * 12;
        u64* src = buf[k & 1];
        u64* dst = buf[(k & 1) ^ 1];

        // ---- stage A: CNOT-layer gather + RY qubits 0..3 (reg bits 3..0) ----
#pragma unroll
        for (int r = 0; r < 16; r++) {
            float2 L = ((const float2*)src)[gbase ^ es(Emap(r << 7))];
            float x = sw ? L.y : L.x;
            float y = sw ? L.x : L.y;
            PACK2(P[r], x, y);
        }
        bfly16(P, 8, cc[0], ss[0], ns[0]);
        bfly16(P, 4, cc[1], ss[1], ns[1]);
        bfly16(P, 2, cc[2], ss[2], ns[2]);
        bfly16(P, 1, cc[3], ss[3], ns[3]);
#pragma unroll
        for (int r = 0; r < 16; r++)
            dst[aA ^ es(r << 7)] = P[r];
        __syncthreads();

        // ---- stage B: RY qubits 4..7 (i bits 7..4 = reg bits 3..0) ----
#pragma unroll
        for (int r = 0; r < 16; r++)
            P[r] = dst[aB ^ es(r << 3)];
        bfly16(P, 8, cc[4], ss[4], ns[4]);
        bfly16(P, 4, cc[5], ss[5], ns[5]);
        bfly16(P, 2, cc[6], ss[6], ns[6]);
        bfly16(P, 1, cc[7], ss[7], ns[7]);
#pragma unroll
        for (int r = 0; r < 16; r++)
            dst[aB ^ es(r << 3)] = P[r];
        __syncthreads();

        // ---- stage C: RY qubits 8..10 (reg bits 2..0) + qubit 11 (SIMD lane) ----
#pragma unroll
        for (int r = 0; r < 16; r++)
            P[r] = dst[aC ^ r];
        bfly16(P, 4, cc[8],  ss[8],  ns[8]);
        bfly16(P, 2, cc[9],  ss[9],  ns[9]);
        bfly16(P, 1, cc[10], ss[10], ns[10]);
        {
            float c, s, n, d_;
            UNPACK2(c, d_, cc[11]);
            UNPACK2(s, d_, ss[11]);
            n = -s;
#pragma unroll
            for (int r = 0; r < 16; r++) {
                float x, y;
                UNPACK2(x, y, P[r]);
                float nx = fmaf(c, x, n * y);
                float ny = fmaf(c, y, s * x);
                PACK2(P[r], nx, ny);
            }
        }
        if (k != DEPTH - 1) {
#pragma unroll
            for (int r = 0; r < 16; r++)
                dst[aC ^ r] = P[r];
            __syncthreads();
        }
    }

    // ---- measurement from registers (tiling C: reg bits = i bits 4..1) ----
    float T = 0.0f, s7 = 0.0f, s8 = 0.0f, s9 = 0.0f;
#pragma unroll
    for (int r = 0; r < 16; r++) {
        float x, y;
        UNPACK2(x, y, P[r]);
        float p2 = fmaf(x, x, y * y);
        T += p2;
        if (!(r & 8)) s7 += p2;   // class 7 <-> i bit 4 = reg bit 3
        if (!(r & 4)) s8 += p2;   // class 8 <-> i bit 3 = reg bit 2
        if (!(r & 2)) s9 += p2;   // class 9 <-> i bit 2 = reg bit 1
    }
    float loc[NCLASS];
#pragma unroll
    for (int p = 0; p < 7; p++)                 // classes 0..6 <-> thread bits 6..0
        loc[p] = ((t >> (6 - p)) & 1) ? -T : T;
    loc[7] = 2.0f * s7 - T;
    loc[8] = 2.0f * s8 - T;
    loc[9] = 2.0f * s9 - T;

#pragma unroll
    for (int p = 0; p < NCLASS; p++) {
        float v = loc[p];
#pragma unroll
        for (int o = 16; o > 0; o >>= 1)
            v += __shfl_xor_sync(0xffffffffu, v, o);
        if ((t & 31) == 0) red[t >> 5][p] = v;
    }
    __syncthreads();
    if (t < NCLASS)
        out[blockIdx.x * NCLASS + t] = (red[0][t] + red[1][t]) + (red[2][t] + red[3][t]);
}

extern "C" void kernel_launch(void* const* d_in, const int* in_sizes, int n_in,
                              void* d_out, int out_size) {
    const float* X = (const float*)d_in[0];   // [4096, 12] fp32
    const float* W = (const float*)d_in[1];   // [8, 12]    fp32
    float* out = (float*)d_out;               // [4096, 10] fp32
    const int batch = in_sizes[0] / 12;
    vqc_kernel<<<batch, NT>>>(X, W, out);
}

// round 4
// speedup vs baseline: 1.6724x; 1.2106x over previous
#include <cuda_runtime.h>

#define DEPTH   8
#define NCLASS  10
#define NT      64
#define NREG    32    // float2 elements per thread; NT*NREG = 2048 = DIM/2

typedef unsigned long long u64;

// GF(2)-linear element swizzle: conflict-free u64 LDS/STS for tilings A, B
// and the CNOT gather pattern (rank-4 verified on all three lane spans).
__device__ __host__ constexpr int Sz(int e) {
    return e ^ ((e >> 5) & 15) ^ (((e >> 10) & 1) << 3);
}
// CNOT-layer composite map in element space: old_e = Emap(new_e).
__device__ __host__ constexpr int Emap(int e) {
    return e ^ (e >> 1) ^ ((e >> 2) & 0x2AA);
}
// per-register constants (compile-time folded in unrolled loops)
__device__ __host__ constexpr int CBr(int r)  { return (r << 5) ^ (r & 15); } // Sz(r<<5)
__device__ __host__ constexpr int CGr(int r)  { return Emap(r); }             // Sz(Emap(r)), r<32
__device__ __host__ constexpr bool SWP(int r) { return ((r ^ (r >> 1)) & 1) != 0; }

#define PACK2(d,x,y)   asm("mov.b64 %0,{%1,%2};" : "=l"(d) : "f"(x),"f"(y))
#define UNPACK2(x,y,d) asm("mov.b64 {%0,%1},%2;" : "=f"(x),"=f"(y) : "l"(d))
#define MUL2(d,a,b)    asm("mul.rn.f32x2 %0,%1,%2;" : "=l"(d) : "l"(a),"l"(b))
#define FMA2(d,a,b,c)  asm("fma.rn.f32x2 %0,%1,%2,%3;" : "=l"(d) : "l"(a),"l"(b),"l"(c))

// Packed lifting RY butterfly on 32 u64 regs along register-bit mask m.
// NP2 = (-tan(phi/2))x2, S2 = (sin phi)x2.
__device__ __forceinline__ void lift32(u64* P, int m, u64 NP2, u64 S2) {
#pragma unroll
    for (int k = 0; k < NREG; k++)
        if (!(k & m)) {
            u64 U, V;
            FMA2(U, NP2, P[k | m], P[k]);      // u  = a0 - p*a1
            FMA2(V, S2,  U,        P[k | m]);  // a1'= a1 + s*u
            FMA2(P[k], NP2, V, U);             // a0'= u - p*a1'
            P[k | m] = V;
        }
}

__global__ __launch_bounds__(NT, 6) void vqc_kernel(const float* __restrict__ X,
                                                    const float* __restrict__ W,
                                                    float* __restrict__ out) {
    __shared__ u64 smP[2048];                 // B-store / gather buffer
    __shared__ u64 smQ[2048];                 // A-store / B-load buffer
    __shared__ u64 CC2[DEPTH * 12], SS2[DEPTH * 12], PP2[DEPTH * 12];
    __shared__ float enc0[12], enc1[12];
    __shared__ float red[2][NCLASS];

    const int t = threadIdx.x;

    // ---- coefficient tables: c, s, -p = -tan(phi/2), phi = W/2 ----
    for (int i = t; i < DEPTH * 12; i += NT) {
        float s_, c_;
        sincosf(0.5f * W[i], &s_, &c_);
        float np = -s_ / (1.0f + c_);
        u64 a, b2, c3;
        PACK2(a, c_, c_);  PACK2(b2, s_, s_);  PACK2(c3, np, np);
        CC2[i] = a;  SS2[i] = b2;  PP2[i] = c3;
    }
    if (t < 12) {
        float s_, c_;
        sincosf(0.5f * X[blockIdx.x * 12 + t], &s_, &c_);
        const float rr = 0.7071067811865476f;
        enc0[t] = (c_ - s_) * rr;
        enc1[t] = (c_ + s_) * rr;
    }
    __syncthreads();

    // ---- per-thread address bases (tilings; all GF(2)-linear) ----
    // Tiling A: e = (t<<5)|r   (regs = e4..0 -> qubits 6..10)
    // Tiling B: e = (t0<<10)|(r<<5)|((t>>1)&31)  (regs = e9..5 -> qubits 1..5)
    const int bA = (t << 5) ^ (t & 15) ^ (((t >> 5) & 1) << 3);
    const int bB = (((t & 1) << 10) | ((t >> 1) & 31)) ^ ((t & 1) << 3);
    int em = t << 5;
    em = em ^ (em >> 1) ^ ((em >> 2) & 0x2AA);
    const int bG = Sz(em);

    // ---- init: product state (H + encoding RY) in tiling B registers ----
    // thread bits: q0<-t0, q6<-t5, q7<-t4, q8<-t3, q9<-t2, q10<-t1
    float base = (t & 1)        ? enc1[0]  : enc0[0];
    base *= ((t >> 5) & 1)      ? enc1[6]  : enc0[6];
    base *= ((t >> 4) & 1)      ? enc1[7]  : enc0[7];
    base *= ((t >> 3) & 1)      ? enc1[8]  : enc0[8];
    base *= ((t >> 2) & 1)      ? enc1[9]  : enc0[9];
    base *= ((t >> 1) & 1)      ? enc1[10] : enc0[10];
    const float bx = base * enc0[11], by = base * enc1[11];

    u64 P[NREG];
#pragma unroll
    for (int r = 0; r < NREG; r++) {
        // reg bits: q1<-r4, q2<-r3, q3<-r2, q4<-r1, q5<-r0
        float rf = (r & 16) ? enc1[1] : enc0[1];
        rf *= (r & 8) ? enc1[2] : enc0[2];
        rf *= (r & 4) ? enc1[3] : enc0[3];
        rf *= (r & 2) ? enc1[4] : enc0[4];
        rf *= (r & 1) ? enc1[5] : enc0[5];
        float x = rf * bx, y = rf * by;
        PACK2(P[r], x, y);
    }

#pragma unroll 1
    for (int k = 0; k < DEPTH; k++) {
        const int kc = k * 12;

        // ---- trip 1: store B, gather (CNOT perm), RY q11 + q6..q10 ----
#pragma unroll
        for (int r = 0; r < NREG; r++)
            smP[bB ^ CBr(r)] = P[r];
        __syncthreads();

        const float np11 = ((const float*)(PP2 + kc + 11))[0];
        const float s11  = ((const float*)(SS2 + kc + 11))[0];
#pragma unroll
        for (int r = 0; r < NREG; r++) {
            float2 L = ((const float2*)smP)[bG ^ CGr(r)];
            float x = SWP(r) ? L.y : L.x;
            float y = SWP(r) ? L.x : L.y;
            // SIMD qubit 11 (lifting, scalar)
            float u = fmaf(np11, y, x);
            float v = fmaf(s11, u, y);
            float w = fmaf(np11, v, u);
            PACK2(P[r], w, v);
        }
        lift32(P, 16, PP2[kc + 6],  SS2[kc + 6]);   // q6  <-> r4
        lift32(P, 8,  PP2[kc + 7],  SS2[kc + 7]);   // q7
        lift32(P, 4,  PP2[kc + 8],  SS2[kc + 8]);   // q8
        lift32(P, 2,  PP2[kc + 9],  SS2[kc + 9]);   // q9
        lift32(P, 1,  PP2[kc + 10], SS2[kc + 10]);  // q10

        // ---- trip 2: store A, load B, RY q1..q5 + shfl qubit 0 ----
#pragma unroll
        for (int r = 0; r < NREG; r++)
            smQ[bA ^ r] = P[r];
        __syncthreads();
#pragma unroll
        for (int r = 0; r < NREG; r++)
            P[r] = smQ[bB ^ CBr(r)];

        lift32(P, 16, PP2[kc + 1], SS2[kc + 1]);    // q1 <-> r4
        lift32(P, 8,  PP2[kc + 2], SS2[kc + 2]);
        lift32(P, 4,  PP2[kc + 3], SS2[kc + 3]);
        lift32(P, 2,  PP2[kc + 4], SS2[kc + 4]);
        lift32(P, 1,  PP2[kc + 5], SS2[kc + 5]);

        // qubit 0 on lane bit t0: standard butterfly via shfl_xor
        {
            const float c0 = ((const float*)(CC2 + kc))[0];
            const float s0 = ((const float*)(SS2 + kc))[0];
            const float se = (t & 1) ? s0 : -s0;
            u64 C2x, SE2;
            PACK2(C2x, c0, c0);
            PACK2(SE2, se, se);
#pragma unroll
            for (int r = 0; r < NREG; r++) {
                u64 part = __shfl_xor_sync(0xffffffffu, P[r], 1);
                u64 tm;
                MUL2(tm, SE2, part);
                FMA2(P[r], C2x, P[r], tm);
            }
        }
        __syncthreads();   // protect smP WAR for next layer's store-B
    }

    // ---- measurement from registers (tiling B) ----
    // class signs: p0<-t0, p1..p5<-r4..r0, p6<-t5, p7<-t4, p8<-t3, p9<-t2
    float T = 0.0f, A1 = 0.0f, A2 = 0.0f, A3 = 0.0f, A4 = 0.0f, A5 = 0.0f;
#pragma unroll
    for (int r = 0; r < NREG; r++) {
        float x, y;
        UNPACK2(x, y, P[r]);
        float p2 = fmaf(y, y, x * x);
        T += p2;
        if (!(r & 16)) A1 += p2;
        if (!(r & 8))  A2 += p2;
        if (!(r & 4))  A3 += p2;
        if (!(r & 2))  A4 += p2;
        if (!(r & 1))  A5 += p2;
    }
    float loc[NCLASS];
    loc[0] = (t & 1)        ? -T : T;
    loc[1] = 2.0f * A1 - T;
    loc[2] = 2.0f * A2 - T;
    loc[3] = 2.0f * A3 - T;
    loc[4] = 2.0f * A4 - T;
    loc[5] = 2.0f * A5 - T;
    loc[6] = ((t >> 5) & 1) ? -T : T;
    loc[7] = ((t >> 4) & 1) ? -T : T;
    loc[8] = ((t >> 3) & 1) ? -T : T;
    loc[9] = ((t >> 2) & 1) ? -T : T;

#pragma unroll
    for (int p = 0; p < NCLASS; p++) {
        float v = loc[p];
#pragma unroll
        for (int o = 16; o > 0; o >>= 1)
            v += __shfl_xor_sync(0xffffffffu, v, o);
        if ((t & 31) == 0) red[t >> 5][p] = v;
    }
    __syncthreads();
    if (t < NCLASS)
        out[blockIdx.x * NCLASS + t] = red[0][t] + red[1][t];
}

extern "C" void kernel_launch(void* const* d_in, const int* in_sizes, int n_in,
                              void* d_out, int out_size) {
    const float* X = (const float*)d_in[0];   // [4096, 12] fp32
    const float* W = (const float*)d_in[1];   // [8, 12]    fp32
    float* out = (float*)d_out;               // [4096, 10] fp32
    const int batch = in_sizes[0] / 12;
    vqc_kernel<<<batch, NT>>>(X, W, out);
}